// round 9
// baseline (speedup 1.0000x reference)
#include <cuda_runtime.h>
#include <cstdint>

#define N_ROUNDS 64
#define HID      256
#define NBATCH   8192
#define KW       64            // 256 k / 4 per int8x4 word
#define TILE_R   64            // batch rows per CTA
#define NTHREADS 512
#define NBLOCKS  (NBATCH / TILE_R)   // 128

#define XS_STRIDE 72           // padded word stride for x (conflict-free IMMA A + dp4a)
#define XS_WORDS  (KW * XS_STRIDE)

// column split: tensor warps (0..7) do [0, C_T), dp4a warps (8..15) do [C_T, 256)
#define C_T      128
#define NSUB     4             // C_T / (4 col-groups * 8)
#define DCOLS    16            // (256 - C_T) / 8 dp4a warps

// Pre-packed ternary matrices: g_M[r][w][h] = M[r][h][4w..4w+3] as int8x4
static __device__ uint32_t g_M[N_ROUNDS * KW * HID];   // 4 MB, L2-resident

__global__ void pack_matrices_kernel(const float* __restrict__ mats) {
    int idx = blockIdx.x * blockDim.x + threadIdx.x;   // 64*256*64 threads
    int w = idx & (KW - 1);
    int h = (idx >> 6) & (HID - 1);
    int r = idx >> 14;
    const float4 v = *reinterpret_cast<const float4*>(
        mats + ((size_t)(r * HID + h) * HID + (w << 2)));
    uint32_t p = ((uint32_t)((int)v.x) & 0xFFu)
               | (((uint32_t)((int)v.y) & 0xFFu) << 8)
               | (((uint32_t)((int)v.z) & 0xFFu) << 16)
               | (((uint32_t)((int)v.w) & 0xFFu) << 24);
    g_M[(r * KW + w) * HID + h] = p;
}

__device__ __forceinline__ void imma(int* c, const uint32_t* a, const uint32_t* b) {
    asm volatile(
        "mma.sync.aligned.m16n8k32.row.col.s32.s8.s8.s32 "
        "{%0,%1,%2,%3}, {%4,%5,%6,%7}, {%8,%9}, {%0,%1,%2,%3};"
        : "+r"(c[0]), "+r"(c[1]), "+r"(c[2]), "+r"(c[3])
        : "r"(a[0]), "r"(a[1]), "r"(a[2]), "r"(a[3]), "r"(b[0]), "r"(b[1]));
}

__global__ __launch_bounds__(NTHREADS, 1) void tenshash_kernel(
    const int*   __restrict__ nonces,   // [8192, 32]
    const float* __restrict__ noise,    // [8192, 64, 256]; nonzero only round 0
    float*       __restrict__ out)      // [8192, 256]
{
    extern __shared__ uint32_t smem[];   // xs ping-pong: 2 x [KW][72] = 36 KB

    const int tid  = threadIdx.x;
    const int lane = tid & 31;
    const int wid  = tid >> 5;
    const int b0   = blockIdx.x * TILE_R;

    // ---- init packed x0 (buffer 0) from nonce bits ----
    for (int i = tid; i < TILE_R * KW; i += NTHREADS) {
        int w   = i & (KW - 1);
        int row = i >> 6;
        int v   = nonces[(b0 + row) * 32 + (w >> 1)];
        int j0  = (w & 1) << 2;
        uint32_t p = ((uint32_t)((v >> j0) & 1))
                   | ((uint32_t)((v >> (j0 + 1)) & 1) << 8)
                   | ((uint32_t)((v >> (j0 + 2)) & 1) << 16)
                   | ((uint32_t)((v >> (j0 + 3)) & 1) << 24);
        smem[w * XS_STRIDE + row] = p;
    }
    __syncthreads();

    const bool is_tensor = (wid < 8);
    // tensor-warp coords
    const int g  = lane >> 2;
    const int tg = lane & 3;
    const int r0t = (wid & 1) * 32;          // batch-row base
    const int n0b = (wid >> 1) * (NSUB * 8); // output-col base: 0,32,64,96
    // dp4a-warp coords
    const int dwid = wid - 8;
    const int c0d  = C_T + dwid * DCOLS;     // 128..240
    const int r0d  = lane << 1;

    int c[2][NSUB][4];
    if (is_tensor) {
        #pragma unroll
        for (int mi = 0; mi < 2; mi++)
            #pragma unroll
            for (int ni = 0; ni < NSUB; ni++)
                #pragma unroll
                for (int t = 0; t < 4; t++) c[mi][ni][t] = 0;
    }

    for (int r = 0; r < N_ROUNDS; r++) {
        const uint32_t* xs  = smem + (r & 1) * XS_WORDS;
        uint32_t*       xsn = smem + ((r + 1) & 1) * XS_WORDS;
        const uint32_t* Mr  = g_M + (size_t)r * (KW * HID);

        if (is_tensor) {
            // ---- tensor path: 32 x 32 tile, cols [0,128); B straight from L2 ----
            uint32_t bq[NSUB][2];
            #pragma unroll
            for (int ni = 0; ni < NSUB; ni++) {           // prefetch kc=0
                const int n = n0b + ni * 8 + g;
                bq[ni][0] = __ldg(&Mr[(tg)     * HID + n]);
                bq[ni][1] = __ldg(&Mr[(4 + tg) * HID + n]);
            }
            #pragma unroll
            for (int kc = 0; kc < 8; kc++) {
                const int wb = kc * 8;
                uint32_t a[2][4], b[NSUB][2];
                #pragma unroll
                for (int ni = 0; ni < NSUB; ni++) {
                    b[ni][0] = bq[ni][0];
                    b[ni][1] = bq[ni][1];
                }
                if (kc < 7) {                              // prefetch kc+1
                    const int wn = wb + 8;
                    #pragma unroll
                    for (int ni = 0; ni < NSUB; ni++) {
                        const int n = n0b + ni * 8 + g;
                        bq[ni][0] = __ldg(&Mr[(wn + tg)     * HID + n]);
                        bq[ni][1] = __ldg(&Mr[(wn + 4 + tg) * HID + n]);
                    }
                }
                #pragma unroll
                for (int mi = 0; mi < 2; mi++) {
                    const int rr = r0t + mi * 16 + g;
                    a[mi][0] = xs[(wb + tg) * XS_STRIDE + rr];
                    a[mi][1] = xs[(wb + tg) * XS_STRIDE + rr + 8];
                    a[mi][2] = xs[(wb + 4 + tg) * XS_STRIDE + rr];
                    a[mi][3] = xs[(wb + 4 + tg) * XS_STRIDE + rr + 8];
                }
                #pragma unroll
                for (int mi = 0; mi < 2; mi++)
                    #pragma unroll
                    for (int ni = 0; ni < NSUB; ni++)
                        imma(c[mi][ni], a[mi], b[ni]);
            }

            // ---- epilogue: (+noise r0) mod 2, repack, store to other buffer ----
            #pragma unroll
            for (int mi = 0; mi < 2; mi++) {
                #pragma unroll
                for (int ni = 0; ni < NSUB; ni++) {
                    int* cc = c[mi][ni];
                    const int rowA = r0t + mi * 16 + g;
                    const int colA = n0b + ni * 8 + tg * 2;
                    if (r == 0) {
                        const float* np  = noise + (size_t)(b0 + rowA) * (N_ROUNDS * HID) + colA;
                        const float* np8 = noise + (size_t)(b0 + rowA + 8) * (N_ROUNDS * HID) + colA;
                        cc[0] += (int)np[0];  cc[1] += (int)np[1];
                        cc[2] += (int)np8[0]; cc[3] += (int)np8[1];
                    }
                    int v0 = cc[0] % 2, v1 = cc[1] % 2, v2 = cc[2] % 2, v3 = cc[3] % 2;
                    cc[0] = cc[1] = cc[2] = cc[3] = 0;
                    if (r + 1 < N_ROUNDS) {
                        uint32_t plo = ((uint32_t)v0 & 0xFFu) | (((uint32_t)v1 & 0xFFu) << 8);
                        uint32_t phi = ((uint32_t)v2 & 0xFFu) | (((uint32_t)v3 & 0xFFu) << 8);
                        uint32_t qlo = __shfl_xor_sync(0xFFFFFFFFu, plo, 1);
                        uint32_t qhi = __shfl_xor_sync(0xFFFFFFFFu, phi, 1);
                        if ((tg & 1) == 0) {
                            const int w = ((n0b + ni * 8) >> 2) + (tg >> 1);
                            xsn[w * XS_STRIDE + rowA]     = (plo & 0xFFFFu) | (qlo << 16);
                            xsn[w * XS_STRIDE + rowA + 8] = (phi & 0xFFFFu) | (qhi << 16);
                        }
                    } else {
                        float* o  = out + (size_t)(b0 + rowA) * HID + colA;
                        float* o8 = out + (size_t)(b0 + rowA + 8) * HID + colA;
                        o[0]  = (float)v0;  o[1]  = (float)v1;
                        o8[0] = (float)v2;  o8[1] = (float)v3;
                    }
                }
            }
        } else {
            // ---- dp4a path: 64 x 16 tile, cols [128,256); M broadcast-LDG from L2 ----
            int acc[2][DCOLS];
            #pragma unroll
            for (int i = 0; i < 2; i++)
                #pragma unroll
                for (int j = 0; j < DCOLS; j++) acc[i][j] = 0;

            #pragma unroll 8
            for (int w = 0; w < KW; w++) {
                uint2 xv = *reinterpret_cast<const uint2*>(&xs[w * XS_STRIDE + r0d]);
                const uint4* mp = reinterpret_cast<const uint4*>(Mr + w * HID + c0d);
                uint32_t mw[DCOLS];
                #pragma unroll
                for (int q = 0; q < DCOLS / 4; q++) {
                    uint4 m = __ldg(mp + q);
                    mw[q * 4 + 0] = m.x; mw[q * 4 + 1] = m.y;
                    mw[q * 4 + 2] = m.z; mw[q * 4 + 3] = m.w;
                }
                #pragma unroll
                for (int j = 0; j < DCOLS; j++) {
                    acc[0][j] = __dp4a((int)xv.x, (int)mw[j], acc[0][j]);
                    acc[1][j] = __dp4a((int)xv.y, (int)mw[j], acc[1][j]);
                }
            }

            if (r == 0) {
                #pragma unroll
                for (int i = 0; i < 2; i++) {
                    const float* np = noise + (size_t)(b0 + r0d + i) * (N_ROUNDS * HID) + c0d;
                    #pragma unroll
                    for (int j = 0; j < DCOLS; j++) acc[i][j] += (int)np[j];
                }
            }

            if (r + 1 < N_ROUNDS) {
                #pragma unroll
                for (int jw = 0; jw < DCOLS / 4; jw++) {
                    uint32_t lo = 0, hi = 0;
                    #pragma unroll
                    for (int t = 0; t < 4; t++) {
                        lo |= ((uint32_t)(acc[0][jw * 4 + t] % 2) & 0xFFu) << (t * 8);
                        hi |= ((uint32_t)(acc[1][jw * 4 + t] % 2) & 0xFFu) << (t * 8);
                    }
                    const int w = (c0d >> 2) + jw;
                    *reinterpret_cast<uint2*>(&xsn[w * XS_STRIDE + r0d]) = make_uint2(lo, hi);
                }
            } else {
                #pragma unroll
                for (int i = 0; i < 2; i++) {
                    float* o = out + (size_t)(b0 + r0d + i) * HID + c0d;
                    #pragma unroll
                    for (int j = 0; j < DCOLS; j++) o[j] = (float)(acc[i][j] % 2);
                }
            }
        }

        __syncthreads();   // single barrier: all xsn writes visible before next round reads
    }
}

extern "C" void kernel_launch(void* const* d_in, const int* in_sizes, int n_in,
                              void* d_out, int out_size) {
    const int*   nonces = (const int*)d_in[0];
    const float* mats   = (const float*)d_in[1];
    const float* noise  = (const float*)d_in[2];
    float*       out    = (float*)d_out;

    const int smem_bytes = 2 * XS_WORDS * 4;   // 36864
    cudaFuncSetAttribute(tenshash_kernel,
                         cudaFuncAttributeMaxDynamicSharedMemorySize, smem_bytes);

    pack_matrices_kernel<<<(N_ROUNDS * HID * KW) / 256, 256>>>(mats);
    tenshash_kernel<<<NBLOCKS, NTHREADS, smem_bytes>>>(nonces, noise, out);
}

// round 10
// speedup vs baseline: 1.5220x; 1.5220x over previous
#include <cuda_runtime.h>
#include <cstdint>

#define N_ROUNDS 64
#define HID      256
#define NBATCH   8192
#define KW       64            // 256 k / 4 per int8x4 word
#define TILE_R   64            // batch rows per CTA
#define NTHREADS 512
#define NBLOCKS  (NBATCH / TILE_R)   // 128

#define XS_STRIDE 72           // padded word stride for x
#define XS_WORDS  (KW * XS_STRIDE)          // 4608
#define MS_STRIDE 264          // padded word stride for M
#define MS_WORDS  (KW * MS_STRIDE)          // 16896
#define MS_BYTES  (MS_WORDS * 4)            // 67584

// column split: tensor warps (0..7) do [0, C_T), dp4a warps (8..15) do [C_T, 256)
#define C_T      160
#define NSUB     5             // C_T / (4 col-groups * 8)
#define DCOLS    12            // (256 - C_T) / 8 dp4a warps

// smem word offsets
#define W_MBAR 0               // 2 mbarriers in [0, 4) words
#define W_XS   8               // xs ping-pong: [8, 8 + 2*4608)
#define W_MS   (W_XS + 2 * XS_WORDS)        // 9224; byte 36896 (16B aligned)
#define SMEM_WORDS (W_MS + 2 * MS_WORDS)    // 43016 -> 172064 B

// Pre-PADDED packed matrices: g_Mp[r][w*264 + h] = M[r][h][4w..4w+3] int8x4
static __device__ __align__(16) uint32_t g_Mp[N_ROUNDS * MS_WORDS];   // ~4.3 MB

__global__ void pack_matrices_kernel(const float* __restrict__ mats) {
    int idx = blockIdx.x * blockDim.x + threadIdx.x;   // 64*256*64 threads
    int w = idx & (KW - 1);
    int h = (idx >> 6) & (HID - 1);
    int r = idx >> 14;
    const float4 v = *reinterpret_cast<const float4*>(
        mats + ((size_t)(r * HID + h) * HID + (w << 2)));
    uint32_t p = ((uint32_t)((int)v.x) & 0xFFu)
               | (((uint32_t)((int)v.y) & 0xFFu) << 8)
               | (((uint32_t)((int)v.z) & 0xFFu) << 16)
               | (((uint32_t)((int)v.w) & 0xFFu) << 24);
    g_Mp[(size_t)r * MS_WORDS + w * MS_STRIDE + h] = p;
}

__device__ __forceinline__ uint32_t smem_u32(const void* p) {
    uint32_t a;
    asm("{ .reg .u64 t; cvta.to.shared.u64 t, %1; cvt.u32.u64 %0, t; }" : "=r"(a) : "l"(p));
    return a;
}
__device__ __forceinline__ void imma(int* c, const uint32_t* a, const uint32_t* b) {
    asm volatile(
        "mma.sync.aligned.m16n8k32.row.col.s32.s8.s8.s32 "
        "{%0,%1,%2,%3}, {%4,%5,%6,%7}, {%8,%9}, {%0,%1,%2,%3};"
        : "+r"(c[0]), "+r"(c[1]), "+r"(c[2]), "+r"(c[3])
        : "r"(a[0]), "r"(a[1]), "r"(a[2]), "r"(a[3]), "r"(b[0]), "r"(b[1]));
}

#define MBAR_INIT(a, c)  asm volatile("mbarrier.init.shared.b64 [%0], %1;" :: "r"(a), "r"(c) : "memory")
#define MBAR_EXPECT_TX(a, b) asm volatile("mbarrier.arrive.expect_tx.shared.b64 _, [%0], %1;" :: "r"(a), "r"(b) : "memory")
#define MBAR_WAIT(a, ph) do { \
    uint32_t _m = (a), _p = (ph), _d; \
    asm volatile("{ .reg .pred p; mbarrier.try_wait.parity.acquire.cta.shared::cta.b64 p, [%1], %2; selp.b32 %0,1,0,p; }" \
        : "=r"(_d) : "r"(_m), "r"(_p) : "memory"); \
    if (!_d) { \
        asm volatile("{ .reg .pred P1; WL%=: mbarrier.try_wait.parity.acquire.cta.shared::cta.b64 P1, [%0], %1, 0x989680; @P1 bra.uni WD%=; bra.uni WL%=; WD%=: }" \
            :: "r"(_m), "r"(_p) : "memory"); \
    } } while (0)
#define BULK_G2S(dst, src, bytes, mbar) \
    asm volatile("cp.async.bulk.shared::cluster.global.mbarrier::complete_tx::bytes [%0], [%1], %2, [%3];" \
        :: "r"(dst), "l"(src), "r"(bytes), "r"(mbar) : "memory")

__global__ __launch_bounds__(NTHREADS, 1) void tenshash_kernel(
    const int*   __restrict__ nonces,   // [8192, 32]
    const float* __restrict__ noise,    // [8192, 64, 256]; nonzero only round 0
    float*       __restrict__ out)      // [8192, 256]
{
    extern __shared__ uint32_t smem[];
    const uint32_t sb = smem_u32(smem);
    const uint32_t mbar[2] = { sb + W_MBAR * 4, sb + W_MBAR * 4 + 8 };
    const uint32_t ms_base[2] = { sb + W_MS * 4, sb + (W_MS + MS_WORDS) * 4 };

    const int tid  = threadIdx.x;
    const int lane = tid & 31;
    const int wid  = tid >> 5;
    const int b0   = blockIdx.x * TILE_R;

    if (tid == 0) {
        MBAR_INIT(mbar[0], 1);
        MBAR_INIT(mbar[1], 1);
    }

    // ---- init packed x0 (buffer 0) from nonce bits ----
    for (int i = tid; i < TILE_R * KW; i += NTHREADS) {
        int w   = i & (KW - 1);
        int row = i >> 6;
        int v   = nonces[(b0 + row) * 32 + (w >> 1)];
        int j0  = (w & 1) << 2;
        uint32_t p = ((uint32_t)((v >> j0) & 1))
                   | ((uint32_t)((v >> (j0 + 1)) & 1) << 8)
                   | ((uint32_t)((v >> (j0 + 2)) & 1) << 16)
                   | ((uint32_t)((v >> (j0 + 3)) & 1) << 24);
        smem[W_XS + w * XS_STRIDE + row] = p;
    }
    __syncthreads();   // mbar init + xs visible

    // kick off round-0 matrix copy
    if (tid == 0) {
        MBAR_EXPECT_TX(mbar[0], MS_BYTES);
        BULK_G2S(ms_base[0], (const void*)g_Mp, MS_BYTES, mbar[0]);
    }

    const bool is_tensor = (wid < 8);
    const int g  = lane >> 2;
    const int tg = lane & 3;
    const int r0t = (wid & 1) * 32;          // batch-row base
    const int n0b = (wid >> 1) * (NSUB * 8); // output-col base: 0,40,80,120
    const int dwid = wid - 8;
    const int c0d  = C_T + dwid * DCOLS;     // 160..244
    const int r0d  = lane << 1;

    int c[2][NSUB][4];
    if (is_tensor) {
        #pragma unroll
        for (int mi = 0; mi < 2; mi++)
            #pragma unroll
            for (int ni = 0; ni < NSUB; ni++)
                #pragma unroll
                for (int t = 0; t < 4; t++) c[mi][ni][t] = 0;
    }

    for (int r = 0; r < N_ROUNDS; r++) {
        const uint32_t* xs  = smem + W_XS + (r & 1) * XS_WORDS;
        uint32_t*       xsn = smem + W_XS + ((r + 1) & 1) * XS_WORDS;
        const uint32_t* ms  = smem + W_MS + (r & 1) * MS_WORDS;

        // issue next round's bulk copy into the other buffer
        // (its round-(r-1) readers all passed the end-of-round barrier already)
        if (tid == 0 && r + 1 < N_ROUNDS) {
            MBAR_EXPECT_TX(mbar[(r + 1) & 1], MS_BYTES);
            BULK_G2S(ms_base[(r + 1) & 1],
                     (const void*)(g_Mp + (size_t)(r + 1) * MS_WORDS),
                     MS_BYTES, mbar[(r + 1) & 1]);
        }

        // wait for this round's matrix
        MBAR_WAIT(mbar[r & 1], (uint32_t)((r >> 1) & 1));

        if (is_tensor) {
            // ---- tensor path: 32 x 40 tile, cols [0,160) ----
            #pragma unroll
            for (int kc = 0; kc < 8; kc++) {
                const int wb = kc * 8;
                uint32_t a[2][4], b[NSUB][2];
                #pragma unroll
                for (int mi = 0; mi < 2; mi++) {
                    const int rr = r0t + mi * 16 + g;
                    a[mi][0] = xs[(wb + tg) * XS_STRIDE + rr];
                    a[mi][1] = xs[(wb + tg) * XS_STRIDE + rr + 8];
                    a[mi][2] = xs[(wb + 4 + tg) * XS_STRIDE + rr];
                    a[mi][3] = xs[(wb + 4 + tg) * XS_STRIDE + rr + 8];
                }
                #pragma unroll
                for (int ni = 0; ni < NSUB; ni++) {
                    const int n = n0b + ni * 8 + g;
                    b[ni][0] = ms[(wb + tg) * MS_STRIDE + n];
                    b[ni][1] = ms[(wb + 4 + tg) * MS_STRIDE + n];
                }
                #pragma unroll
                for (int mi = 0; mi < 2; mi++)
                    #pragma unroll
                    for (int ni = 0; ni < NSUB; ni++)
                        imma(c[mi][ni], a[mi], b[ni]);
            }

            // ---- epilogue: (+noise r0) mod 2, repack, store to other buffer ----
            #pragma unroll
            for (int mi = 0; mi < 2; mi++) {
                #pragma unroll
                for (int ni = 0; ni < NSUB; ni++) {
                    int* cc = c[mi][ni];
                    const int rowA = r0t + mi * 16 + g;
                    const int colA = n0b + ni * 8 + tg * 2;
                    if (r == 0) {
                        const float* np  = noise + (size_t)(b0 + rowA) * (N_ROUNDS * HID) + colA;
                        const float* np8 = noise + (size_t)(b0 + rowA + 8) * (N_ROUNDS * HID) + colA;
                        cc[0] += (int)np[0];  cc[1] += (int)np[1];
                        cc[2] += (int)np8[0]; cc[3] += (int)np8[1];
                    }
                    int v0 = cc[0] % 2, v1 = cc[1] % 2, v2 = cc[2] % 2, v3 = cc[3] % 2;
                    cc[0] = cc[1] = cc[2] = cc[3] = 0;
                    if (r + 1 < N_ROUNDS) {
                        uint32_t plo = ((uint32_t)v0 & 0xFFu) | (((uint32_t)v1 & 0xFFu) << 8);
                        uint32_t phi = ((uint32_t)v2 & 0xFFu) | (((uint32_t)v3 & 0xFFu) << 8);
                        uint32_t qlo = __shfl_xor_sync(0xFFFFFFFFu, plo, 1);
                        uint32_t qhi = __shfl_xor_sync(0xFFFFFFFFu, phi, 1);
                        if ((tg & 1) == 0) {
                            const int w = ((n0b + ni * 8) >> 2) + (tg >> 1);
                            xsn[w * XS_STRIDE + rowA]     = (plo & 0xFFFFu) | (qlo << 16);
                            xsn[w * XS_STRIDE + rowA + 8] = (phi & 0xFFFFu) | (qhi << 16);
                        }
                    } else {
                        float* o  = out + (size_t)(b0 + rowA) * HID + colA;
                        float* o8 = out + (size_t)(b0 + rowA + 8) * HID + colA;
                        o[0]  = (float)v0;  o[1]  = (float)v1;
                        o8[0] = (float)v2;  o8[1] = (float)v3;
                    }
                }
            }
        } else {
            // ---- dp4a path: 64 x 12 tile, cols [160,256) ----
            int acc[2][DCOLS];
            #pragma unroll
            for (int i = 0; i < 2; i++)
                #pragma unroll
                for (int j = 0; j < DCOLS; j++) acc[i][j] = 0;

            #pragma unroll 8
            for (int w = 0; w < KW; w++) {
                uint2 xv = *reinterpret_cast<const uint2*>(&xs[w * XS_STRIDE + r0d]);
                const uint4* mp = reinterpret_cast<const uint4*>(&ms[w * MS_STRIDE + c0d]);
                uint32_t mw[DCOLS];
                #pragma unroll
                for (int q = 0; q < DCOLS / 4; q++) {
                    uint4 m = mp[q];
                    mw[q * 4 + 0] = m.x; mw[q * 4 + 1] = m.y;
                    mw[q * 4 + 2] = m.z; mw[q * 4 + 3] = m.w;
                }
                #pragma unroll
                for (int j = 0; j < DCOLS; j++) {
                    acc[0][j] = __dp4a((int)xv.x, (int)mw[j], acc[0][j]);
                    acc[1][j] = __dp4a((int)xv.y, (int)mw[j], acc[1][j]);
                }
            }

            if (r == 0) {
                #pragma unroll
                for (int i = 0; i < 2; i++) {
                    const float* np = noise + (size_t)(b0 + r0d + i) * (N_ROUNDS * HID) + c0d;
                    #pragma unroll
                    for (int j = 0; j < DCOLS; j++) acc[i][j] += (int)np[j];
                }
            }

            if (r + 1 < N_ROUNDS) {
                #pragma unroll
                for (int jw = 0; jw < DCOLS / 4; jw++) {
                    uint32_t lo = 0, hi = 0;
                    #pragma unroll
                    for (int t = 0; t < 4; t++) {
                        lo |= ((uint32_t)(acc[0][jw * 4 + t] % 2) & 0xFFu) << (t * 8);
                        hi |= ((uint32_t)(acc[1][jw * 4 + t] % 2) & 0xFFu) << (t * 8);
                    }
                    const int w = (c0d >> 2) + jw;
                    *reinterpret_cast<uint2*>(&xsn[w * XS_STRIDE + r0d]) = make_uint2(lo, hi);
                }
            } else {
                #pragma unroll
                for (int i = 0; i < 2; i++) {
                    float* o = out + (size_t)(b0 + r0d + i) * HID + c0d;
                    #pragma unroll
                    for (int j = 0; j < DCOLS; j++) o[j] = (float)(acc[i][j] % 2);
                }
            }
        }

        __syncthreads();   // xsn writes + ms reads complete before next round
    }
}

extern "C" void kernel_launch(void* const* d_in, const int* in_sizes, int n_in,
                              void* d_out, int out_size) {
    const int*   nonces = (const int*)d_in[0];
    const float* mats   = (const float*)d_in[1];
    const float* noise  = (const float*)d_in[2];
    float*       out    = (float*)d_out;

    const int smem_bytes = SMEM_WORDS * 4;   // 172064
    cudaFuncSetAttribute(tenshash_kernel,
                         cudaFuncAttributeMaxDynamicSharedMemorySize, smem_bytes);

    pack_matrices_kernel<<<(N_ROUNDS * HID * KW) / 256, 256>>>(mats);
    tenshash_kernel<<<NBLOCKS, NTHREADS, smem_bytes>>>(nonces, noise, out);
}

// round 11
// speedup vs baseline: 1.6288x; 1.0701x over previous
#include <cuda_runtime.h>
#include <cstdint>

#define N_ROUNDS 64
#define HID      256
#define NBATCH   8192
#define KW       64            // 256 k / 4 per int8x4 word
#define TILE_R   64            // batch rows per CTA
#define NTHREADS 512
#define NBLOCKS  (NBATCH / TILE_R)   // 128

#define XS_STRIDE 72           // padded word stride for x
#define XS_WORDS  (KW * XS_STRIDE)          // 4608
#define MS_STRIDE 264          // padded word stride for M
#define MS_WORDS  (KW * MS_STRIDE)          // 16896
#define MS_BYTES  (MS_WORDS * 4)            // 67584

// column split:
//   tensor warps 0..7 : IMMA cols [0,128) + dp4a cols [224,256) (4 each)
//   dp4a  warps 8..15 : cols [128,224) (12 each)
#define C_T      128
#define NSUB     4             // 128 / (4 col-groups * 8)
#define DCOLS    12
#define TCOLS    4             // dp4a cols per tensor warp
#define C_TD     224           // base of tensor-warp dp4a region

// smem word offsets
#define W_MBAR 0
#define W_XS   8
#define W_MS   (W_XS + 2 * XS_WORDS)
#define SMEM_WORDS (W_MS + 2 * MS_WORDS)    // 43016 -> 172064 B

static __device__ __align__(16) uint32_t g_Mp[N_ROUNDS * MS_WORDS];   // ~4.3 MB

__global__ void pack_matrices_kernel(const float* __restrict__ mats) {
    int idx = blockIdx.x * blockDim.x + threadIdx.x;   // 64*256*64 threads
    int w = idx & (KW - 1);
    int h = (idx >> 6) & (HID - 1);
    int r = idx >> 14;
    const float4 v = *reinterpret_cast<const float4*>(
        mats + ((size_t)(r * HID + h) * HID + (w << 2)));
    uint32_t p = ((uint32_t)((int)v.x) & 0xFFu)
               | (((uint32_t)((int)v.y) & 0xFFu) << 8)
               | (((uint32_t)((int)v.z) & 0xFFu) << 16)
               | (((uint32_t)((int)v.w) & 0xFFu) << 24);
    g_Mp[(size_t)r * MS_WORDS + w * MS_STRIDE + h] = p;
}

__device__ __forceinline__ uint32_t smem_u32(const void* p) {
    uint32_t a;
    asm("{ .reg .u64 t; cvta.to.shared.u64 t, %1; cvt.u32.u64 %0, t; }" : "=r"(a) : "l"(p));
    return a;
}
__device__ __forceinline__ void imma(int* c, const uint32_t* a, const uint32_t* b) {
    asm volatile(
        "mma.sync.aligned.m16n8k32.row.col.s32.s8.s8.s32 "
        "{%0,%1,%2,%3}, {%4,%5,%6,%7}, {%8,%9}, {%0,%1,%2,%3};"
        : "+r"(c[0]), "+r"(c[1]), "+r"(c[2]), "+r"(c[3])
        : "r"(a[0]), "r"(a[1]), "r"(a[2]), "r"(a[3]), "r"(b[0]), "r"(b[1]));
}

#define MBAR_INIT(a, c)  asm volatile("mbarrier.init.shared.b64 [%0], %1;" :: "r"(a), "r"(c) : "memory")
#define MBAR_EXPECT_TX(a, b) asm volatile("mbarrier.arrive.expect_tx.shared.b64 _, [%0], %1;" :: "r"(a), "r"(b) : "memory")
#define MBAR_WAIT(a, ph) do { \
    uint32_t _m = (a), _p = (ph), _d; \
    asm volatile("{ .reg .pred p; mbarrier.try_wait.parity.acquire.cta.shared::cta.b64 p, [%1], %2; selp.b32 %0,1,0,p; }" \
        : "=r"(_d) : "r"(_m), "r"(_p) : "memory"); \
    if (!_d) { \
        asm volatile("{ .reg .pred P1; WL%=: mbarrier.try_wait.parity.acquire.cta.shared::cta.b64 P1, [%0], %1, 0x989680; @P1 bra.uni WD%=; bra.uni WL%=; WD%=: }" \
            :: "r"(_m), "r"(_p) : "memory"); \
    } } while (0)
#define BULK_G2S(dst, src, bytes, mbar) \
    asm volatile("cp.async.bulk.shared::cluster.global.mbarrier::complete_tx::bytes [%0], [%1], %2, [%3];" \
        :: "r"(dst), "l"(src), "r"(bytes), "r"(mbar) : "memory")

__global__ __launch_bounds__(NTHREADS, 1) void tenshash_kernel(
    const int*   __restrict__ nonces,   // [8192, 32]
    const float* __restrict__ noise,    // [8192, 64, 256]; nonzero only round 0
    float*       __restrict__ out)      // [8192, 256]
{
    extern __shared__ uint32_t smem[];
    const uint32_t sb = smem_u32(smem);
    const uint32_t mbar[2] = { sb + W_MBAR * 4, sb + W_MBAR * 4 + 8 };
    const uint32_t ms_base[2] = { sb + W_MS * 4, sb + (W_MS + MS_WORDS) * 4 };

    const int tid  = threadIdx.x;
    const int lane = tid & 31;
    const int wid  = tid >> 5;
    const int b0   = blockIdx.x * TILE_R;

    if (tid == 0) {
        MBAR_INIT(mbar[0], 1);
        MBAR_INIT(mbar[1], 1);
    }

    // ---- init packed x0 (buffer 0) from nonce bits ----
    for (int i = tid; i < TILE_R * KW; i += NTHREADS) {
        int w   = i & (KW - 1);
        int row = i >> 6;
        int v   = nonces[(b0 + row) * 32 + (w >> 1)];
        int j0  = (w & 1) << 2;
        uint32_t p = ((uint32_t)((v >> j0) & 1))
                   | ((uint32_t)((v >> (j0 + 1)) & 1) << 8)
                   | ((uint32_t)((v >> (j0 + 2)) & 1) << 16)
                   | ((uint32_t)((v >> (j0 + 3)) & 1) << 24);
        smem[W_XS + w * XS_STRIDE + row] = p;
    }
    __syncthreads();   // mbar init + xs visible

    if (tid == 0) {
        MBAR_EXPECT_TX(mbar[0], MS_BYTES);
        BULK_G2S(ms_base[0], (const void*)g_Mp, MS_BYTES, mbar[0]);
    }

    const bool is_tensor = (wid < 8);
    const int g  = lane >> 2;
    const int tg = lane & 3;
    const int r0t = (wid & 1) * 32;          // IMMA batch-row base
    const int n0b = (wid >> 1) * (NSUB * 8); // IMMA col base: 0,32,64,96
    const int c0t = C_TD + wid * TCOLS;      // tensor warp's dp4a cols: 224..252
    const int dwid = wid - 8;
    const int c0d  = C_T + dwid * DCOLS;     // dedicated dp4a cols: 128..212
    const int r0d  = lane << 1;              // dp4a rows (both kinds)

    int c[2][NSUB][4];
    if (is_tensor) {
        #pragma unroll
        for (int mi = 0; mi < 2; mi++)
            #pragma unroll
            for (int ni = 0; ni < NSUB; ni++)
                #pragma unroll
                for (int t = 0; t < 4; t++) c[mi][ni][t] = 0;
    }

    for (int r = 0; r < N_ROUNDS; r++) {
        const uint32_t* xs  = smem + W_XS + (r & 1) * XS_WORDS;
        uint32_t*       xsn = smem + W_XS + ((r + 1) & 1) * XS_WORDS;
        const uint32_t* ms  = smem + W_MS + (r & 1) * MS_WORDS;

        if (tid == 0 && r + 1 < N_ROUNDS) {
            MBAR_EXPECT_TX(mbar[(r + 1) & 1], MS_BYTES);
            BULK_G2S(ms_base[(r + 1) & 1],
                     (const void*)(g_Mp + (size_t)(r + 1) * MS_WORDS),
                     MS_BYTES, mbar[(r + 1) & 1]);
        }
        MBAR_WAIT(mbar[r & 1], (uint32_t)((r >> 1) & 1));

        if (is_tensor) {
            // ---- IMMA cols [0,128) + interleaved dp4a cols [c0t, c0t+4) ----
            int acc[2][TCOLS];
            #pragma unroll
            for (int i = 0; i < 2; i++)
                #pragma unroll
                for (int j = 0; j < TCOLS; j++) acc[i][j] = 0;

            #pragma unroll
            for (int kc = 0; kc < 8; kc++) {
                const int wb = kc * 8;
                uint32_t a[2][4], b[NSUB][2];
                #pragma unroll
                for (int mi = 0; mi < 2; mi++) {
                    const int rr = r0t + mi * 16 + g;
                    a[mi][0] = xs[(wb + tg) * XS_STRIDE + rr];
                    a[mi][1] = xs[(wb + tg) * XS_STRIDE + rr + 8];
                    a[mi][2] = xs[(wb + 4 + tg) * XS_STRIDE + rr];
                    a[mi][3] = xs[(wb + 4 + tg) * XS_STRIDE + rr + 8];
                }
                #pragma unroll
                for (int ni = 0; ni < NSUB; ni++) {
                    const int n = n0b + ni * 8 + g;
                    b[ni][0] = ms[(wb + tg) * MS_STRIDE + n];
                    b[ni][1] = ms[(wb + 4 + tg) * MS_STRIDE + n];
                }
                #pragma unroll
                for (int mi = 0; mi < 2; mi++)
                    #pragma unroll
                    for (int ni = 0; ni < NSUB; ni++)
                        imma(c[mi][ni], a[mi], b[ni]);

                // interleaved dp4a: 8 k-words per kc, issued while IMMAs drain
                #pragma unroll
                for (int w2 = 0; w2 < 8; w2++) {
                    const int w = wb + w2;
                    uint2 xv = *reinterpret_cast<const uint2*>(&xs[w * XS_STRIDE + r0d]);
                    uint4 m  = *reinterpret_cast<const uint4*>(&ms[w * MS_STRIDE + c0t]);
                    acc[0][0] = __dp4a((int)xv.x, (int)m.x, acc[0][0]);
                    acc[0][1] = __dp4a((int)xv.x, (int)m.y, acc[0][1]);
                    acc[0][2] = __dp4a((int)xv.x, (int)m.z, acc[0][2]);
                    acc[0][3] = __dp4a((int)xv.x, (int)m.w, acc[0][3]);
                    acc[1][0] = __dp4a((int)xv.y, (int)m.x, acc[1][0]);
                    acc[1][1] = __dp4a((int)xv.y, (int)m.y, acc[1][1]);
                    acc[1][2] = __dp4a((int)xv.y, (int)m.z, acc[1][2]);
                    acc[1][3] = __dp4a((int)xv.y, (int)m.w, acc[1][3]);
                }
            }

            // ---- dp4a epilogue (cols c0t..c0t+3) ----
            if (r == 0) {
                #pragma unroll
                for (int i = 0; i < 2; i++) {
                    const float* np = noise + (size_t)(b0 + r0d + i) * (N_ROUNDS * HID) + c0t;
                    #pragma unroll
                    for (int j = 0; j < TCOLS; j++) acc[i][j] += (int)np[j];
                }
            }
            if (r + 1 < N_ROUNDS) {
                uint32_t lo = 0, hi = 0;
                #pragma unroll
                for (int t = 0; t < 4; t++) {
                    lo |= ((uint32_t)(acc[0][t] % 2) & 0xFFu) << (t * 8);
                    hi |= ((uint32_t)(acc[1][t] % 2) & 0xFFu) << (t * 8);
                }
                const int w = c0t >> 2;
                *reinterpret_cast<uint2*>(&xsn[w * XS_STRIDE + r0d]) = make_uint2(lo, hi);
            } else {
                #pragma unroll
                for (int i = 0; i < 2; i++) {
                    float* o = out + (size_t)(b0 + r0d + i) * HID + c0t;
                    #pragma unroll
                    for (int j = 0; j < TCOLS; j++) o[j] = (float)(acc[i][j] % 2);
                }
            }

            // ---- IMMA epilogue: (+noise r0) mod 2, repack, store ----
            #pragma unroll
            for (int mi = 0; mi < 2; mi++) {
                #pragma unroll
                for (int ni = 0; ni < NSUB; ni++) {
                    int* cc = c[mi][ni];
                    const int rowA = r0t + mi * 16 + g;
                    const int colA = n0b + ni * 8 + tg * 2;
                    if (r == 0) {
                        const float* np  = noise + (size_t)(b0 + rowA) * (N_ROUNDS * HID) + colA;
                        const float* np8 = noise + (size_t)(b0 + rowA + 8) * (N_ROUNDS * HID) + colA;
                        cc[0] += (int)np[0];  cc[1] += (int)np[1];
                        cc[2] += (int)np8[0]; cc[3] += (int)np8[1];
                    }
                    int v0 = cc[0] % 2, v1 = cc[1] % 2, v2 = cc[2] % 2, v3 = cc[3] % 2;
                    cc[0] = cc[1] = cc[2] = cc[3] = 0;
                    if (r + 1 < N_ROUNDS) {
                        uint32_t plo = ((uint32_t)v0 & 0xFFu) | (((uint32_t)v1 & 0xFFu) << 8);
                        uint32_t phi = ((uint32_t)v2 & 0xFFu) | (((uint32_t)v3 & 0xFFu) << 8);
                        uint32_t qlo = __shfl_xor_sync(0xFFFFFFFFu, plo, 1);
                        uint32_t qhi = __shfl_xor_sync(0xFFFFFFFFu, phi, 1);
                        if ((tg & 1) == 0) {
                            const int w = ((n0b + ni * 8) >> 2) + (tg >> 1);
                            xsn[w * XS_STRIDE + rowA]     = (plo & 0xFFFFu) | (qlo << 16);
                            xsn[w * XS_STRIDE + rowA + 8] = (phi & 0xFFFFu) | (qhi << 16);
                        }
                    } else {
                        float* o  = out + (size_t)(b0 + rowA) * HID + colA;
                        float* o8 = out + (size_t)(b0 + rowA + 8) * HID + colA;
                        o[0]  = (float)v0;  o[1]  = (float)v1;
                        o8[0] = (float)v2;  o8[1] = (float)v3;
                    }
                }
            }
        } else {
            // ---- dedicated dp4a path: 64 x 12 tile, cols [128,224) ----
            int acc[2][DCOLS];
            #pragma unroll
            for (int i = 0; i < 2; i++)
                #pragma unroll
                for (int j = 0; j < DCOLS; j++) acc[i][j] = 0;

            #pragma unroll 8
            for (int w = 0; w < KW; w++) {
                uint2 xv = *reinterpret_cast<const uint2*>(&xs[w * XS_STRIDE + r0d]);
                const uint4* mp = reinterpret_cast<const uint4*>(&ms[w * MS_STRIDE + c0d]);
                uint32_t mw[DCOLS];
                #pragma unroll
                for (int q = 0; q < DCOLS / 4; q++) {
                    uint4 m = mp[q];
                    mw[q * 4 + 0] = m.x; mw[q * 4 + 1] = m.y;
                    mw[q * 4 + 2] = m.z; mw[q * 4 + 3] = m.w;
                }
                #pragma unroll
                for (int j = 0; j < DCOLS; j++) {
                    acc[0][j] = __dp4a((int)xv.x, (int)mw[j], acc[0][j]);
                    acc[1][j] = __dp4a((int)xv.y, (int)mw[j], acc[1][j]);
                }
            }

            if (r == 0) {
                #pragma unroll
                for (int i = 0; i < 2; i++) {
                    const float* np = noise + (size_t)(b0 + r0d + i) * (N_ROUNDS * HID) + c0d;
                    #pragma unroll
                    for (int j = 0; j < DCOLS; j++) acc[i][j] += (int)np[j];
                }
            }

            if (r + 1 < N_ROUNDS) {
                #pragma unroll
                for (int jw = 0; jw < DCOLS / 4; jw++) {
                    uint32_t lo = 0, hi = 0;
                    #pragma unroll
                    for (int t = 0; t < 4; t++) {
                        lo |= ((uint32_t)(acc[0][jw * 4 + t] % 2) & 0xFFu) << (t * 8);
                        hi |= ((uint32_t)(acc[1][jw * 4 + t] % 2) & 0xFFu) << (t * 8);
                    }
                    const int w = (c0d >> 2) + jw;
                    *reinterpret_cast<uint2*>(&xsn[w * XS_STRIDE + r0d]) = make_uint2(lo, hi);
                }
            } else {
                #pragma unroll
                for (int i = 0; i < 2; i++) {
                    float* o = out + (size_t)(b0 + r0d + i) * HID + c0d;
                    #pragma unroll
                    for (int j = 0; j < DCOLS; j++) o[j] = (float)(acc[i][j] % 2);
                }
            }
        }

        __syncthreads();   // xsn writes + ms reads complete before next round
    }
}

extern "C" void kernel_launch(void* const* d_in, const int* in_sizes, int n_in,
                              void* d_out, int out_size) {
    const int*   nonces = (const int*)d_in[0];
    const float* mats   = (const float*)d_in[1];
    const float* noise  = (const float*)d_in[2];
    float*       out    = (float*)d_out;

    const int smem_bytes = SMEM_WORDS * 4;   // 172064
    cudaFuncSetAttribute(tenshash_kernel,
                         cudaFuncAttributeMaxDynamicSharedMemorySize, smem_bytes);

    pack_matrices_kernel<<<(N_ROUNDS * HID * KW) / 256, 256>>>(mats);
    tenshash_kernel<<<NBLOCKS, NTHREADS, smem_bytes>>>(nonces, noise, out);
}